// round 1
// baseline (speedup 1.0000x reference)
#include <cuda_runtime.h>
#include <cuda_bf16.h>
#include <math.h>

// ---------------------------------------------------------------------------
// ALiBi self-attention, fp32. B=2, T=2048, D=1024, H=16, hd=64.
// Output = concat(out [B,T,D], attn [B,H,T,T]) fp32 (attn skipped if out_size
// says it isn't checked).
//
// Key structural facts exploited:
//  * ALIBI_SLOPE=1.0 + causal mask => softmax weights underflow to EXACT fp32
//    zero beyond key-distance ~104 (reference computes exp(s - max) in fp32,
//    spread of raw scores <= ~12, so distance >= 193 gives exp(<= -181) == 0).
//    We compute a 224-wide band per 32-query tile; everything else is zero,
//    written directly (full-row writes merge the "memset" with the band).
//  * Four dense 4096x1024x1024 GEMMs (QKV projections + output projection)
//    are done with a register-blocked fp32 SGEMM (tensor-core port is the
//    next optimization once accuracy headroom is measured).
// ---------------------------------------------------------------------------

#define B_    2
#define T_    2048
#define D_    1024
#define H_    16
#define HD_   64
#define MROWS (B_ * T_)                       // 4096
#define OUT_ELEMS ((size_t)MROWS * D_)        // 4,194,304
#define ATTN_ELEMS ((size_t)B_ * H_ * T_ * T_)// 134,217,728

#define QT    32      // queries per attention block
#define WBACK 192     // key lookback beyond tile start
#define MAXNK (WBACK + QT)  // 224 keys max per tile

// Scratch (device globals: allocation-free rule)
__device__ float g_Q[MROWS * D_];
__device__ float g_K[MROWS * D_];
__device__ float g_V[MROWS * D_];
__device__ float g_P[MROWS * D_];

// ---------------------------------------------------------------------------
// C[m][n] = sum_k A[m][k] * W[n][k] + bias[n]   (i.e. C = A @ W^T + b)
// BM=BN=64, BK=16, 256 threads, 4x4 per-thread microtile.
// M,N multiples of 64; K multiple of 16. No guards needed for our shapes.
// ---------------------------------------------------------------------------
__global__ void __launch_bounds__(256) sgemm_nt_bias(
    const float* __restrict__ A, const float* __restrict__ W,
    const float* __restrict__ bias, float* __restrict__ C,
    int M, int N, int K)
{
    __shared__ float As[16][64 + 1];
    __shared__ float Bs[16][64 + 1];

    const int bm = blockIdx.y * 64;
    const int bn = blockIdx.x * 64;
    const int tid = threadIdx.x;

    const int lr = tid >> 2;          // 0..63 row within tile
    const int lk = (tid & 3) << 2;    // 0,4,8,12 k-offset (float4)
    const int ty = tid >> 4;          // 0..15
    const int tx = tid & 15;          // 0..15

    const float* Aptr = A + (size_t)(bm + lr) * K + lk;
    const float* Wptr = W + (size_t)(bn + lr) * K + lk;

    float acc[4][4];
#pragma unroll
    for (int i = 0; i < 4; i++)
#pragma unroll
        for (int j = 0; j < 4; j++) acc[i][j] = 0.f;

    for (int k0 = 0; k0 < K; k0 += 16) {
        float4 a4 = *(const float4*)(Aptr + k0);
        float4 b4 = *(const float4*)(Wptr + k0);
        As[lk + 0][lr] = a4.x; As[lk + 1][lr] = a4.y;
        As[lk + 2][lr] = a4.z; As[lk + 3][lr] = a4.w;
        Bs[lk + 0][lr] = b4.x; Bs[lk + 1][lr] = b4.y;
        Bs[lk + 2][lr] = b4.z; Bs[lk + 3][lr] = b4.w;
        __syncthreads();

#pragma unroll
        for (int kk = 0; kk < 16; kk++) {
            float a0 = As[kk][ty * 4 + 0];
            float a1 = As[kk][ty * 4 + 1];
            float a2 = As[kk][ty * 4 + 2];
            float a3 = As[kk][ty * 4 + 3];
            float b0 = Bs[kk][tx * 4 + 0];
            float b1 = Bs[kk][tx * 4 + 1];
            float b2 = Bs[kk][tx * 4 + 2];
            float b3 = Bs[kk][tx * 4 + 3];
            acc[0][0] += a0 * b0; acc[0][1] += a0 * b1; acc[0][2] += a0 * b2; acc[0][3] += a0 * b3;
            acc[1][0] += a1 * b0; acc[1][1] += a1 * b1; acc[1][2] += a1 * b2; acc[1][3] += a1 * b3;
            acc[2][0] += a2 * b0; acc[2][1] += a2 * b1; acc[2][2] += a2 * b2; acc[2][3] += a2 * b3;
            acc[3][0] += a3 * b0; acc[3][1] += a3 * b1; acc[3][2] += a3 * b2; acc[3][3] += a3 * b3;
        }
        __syncthreads();
    }

#pragma unroll
    for (int i = 0; i < 4; i++) {
        size_t row = (size_t)(bm + ty * 4 + i) * N + bn + tx * 4;
#pragma unroll
        for (int j = 0; j < 4; j++)
            C[row + j] = acc[i][j] + bias[bn + tx * 4 + j];
    }
}

// ---------------------------------------------------------------------------
// Banded attention. Grid: (T/QT, H, B), 256 threads.
// Each block: 32 queries of one (b,h). Keys in [jlo, q0+31], jlo=max(0,q0-192).
// Computes scores, ALiBi+causal softmax, writes FULL attn rows (zeros outside
// the band), and accumulates attn @ V into g_P with [B*T, H*hd] layout.
// ---------------------------------------------------------------------------
__global__ void __launch_bounds__(256) attn_banded_kernel(
    const float* __restrict__ Q, const float* __restrict__ K,
    const float* __restrict__ V, float* __restrict__ P,
    float* __restrict__ attn_out, int has_attn)
{
    __shared__ float Qs[QT][HD_ + 1];
    __shared__ float KVs[QT][HD_ + 1];
    __shared__ float Sc[QT][MAXNK + 1];

    const int b  = blockIdx.z;
    const int h  = blockIdx.y;
    const int q0 = blockIdx.x * QT;
    const int tid = threadIdx.x;
    const int qr = tid >> 3;        // 0..31 : query row / load row
    const int l8 = tid & 7;         // 0..7  : lane within row group

    const int jlo = (q0 - WBACK > 0) ? (q0 - WBACK) : 0;
    const int nk  = q0 + QT - jlo;  // always a multiple of 32 here (<=224)

    // ---- load Q tile [32 x 64] ----
    {
        const float* src = Q + (size_t)(b * T_ + q0 + qr) * D_ + h * HD_ + l8 * 8;
        float4 v0 = *(const float4*)(src);
        float4 v1 = *(const float4*)(src + 4);
        Qs[qr][l8 * 8 + 0] = v0.x; Qs[qr][l8 * 8 + 1] = v0.y;
        Qs[qr][l8 * 8 + 2] = v0.z; Qs[qr][l8 * 8 + 3] = v0.w;
        Qs[qr][l8 * 8 + 4] = v1.x; Qs[qr][l8 * 8 + 5] = v1.y;
        Qs[qr][l8 * 8 + 6] = v1.z; Qs[qr][l8 * 8 + 7] = v1.w;
    }

    // ---- scores: Q @ K^T over the band, chunk 32 keys at a time ----
    const int jb = l8 * 4;  // this thread computes 4 key columns for row qr
    for (int c0 = 0; c0 < nk; c0 += QT) {
        __syncthreads();
        {   // load K chunk rows [jlo+c0 .. +31]
            const float* src = K + (size_t)(b * T_ + jlo + c0 + qr) * D_ + h * HD_ + l8 * 8;
            float4 v0 = *(const float4*)(src);
            float4 v1 = *(const float4*)(src + 4);
            KVs[qr][l8 * 8 + 0] = v0.x; KVs[qr][l8 * 8 + 1] = v0.y;
            KVs[qr][l8 * 8 + 2] = v0.z; KVs[qr][l8 * 8 + 3] = v0.w;
            KVs[qr][l8 * 8 + 4] = v1.x; KVs[qr][l8 * 8 + 5] = v1.y;
            KVs[qr][l8 * 8 + 6] = v1.z; KVs[qr][l8 * 8 + 7] = v1.w;
        }
        __syncthreads();

        float s0 = 0.f, s1 = 0.f, s2 = 0.f, s3 = 0.f;
#pragma unroll
        for (int d = 0; d < HD_; d++) {
            float a = Qs[qr][d];
            s0 += a * KVs[jb + 0][d];
            s1 += a * KVs[jb + 1][d];
            s2 += a * KVs[jb + 2][d];
            s3 += a * KVs[jb + 3][d];
        }
        Sc[qr][c0 + jb + 0] = s0 * 0.125f;
        Sc[qr][c0 + jb + 1] = s1 * 0.125f;
        Sc[qr][c0 + jb + 2] = s2 * 0.125f;
        Sc[qr][c0 + jb + 3] = s3 * 0.125f;
    }
    __syncthreads();

    // ---- softmax per query row (8 lanes cooperate) ----
    const int i = q0 + qr;
    float m = -1e30f;
    for (int idx = l8; idx < nk; idx += 8) {
        int j = jlo + idx;
        float s = (j <= i) ? (Sc[qr][idx] - (float)(i - j)) : -1e30f;
        Sc[qr][idx] = s;
        m = fmaxf(m, s);
    }
#pragma unroll
    for (int o = 4; o >= 1; o >>= 1)
        m = fmaxf(m, __shfl_xor_sync(0xffffffffu, m, o, 8));

    float sum = 0.f;
    for (int idx = l8; idx < nk; idx += 8) {
        float s = Sc[qr][idx];
        float e = (s > -1e29f) ? expf(s - m) : 0.f;
        Sc[qr][idx] = e;
        sum += e;
    }
#pragma unroll
    for (int o = 4; o >= 1; o >>= 1)
        sum += __shfl_xor_sync(0xffffffffu, sum, o, 8);
    float inv = 1.f / sum;
    for (int idx = l8; idx < nk; idx += 8)
        Sc[qr][idx] *= inv;
    __syncthreads();

    // ---- write full attn row (band values + zeros elsewhere) ----
    if (has_attn) {
        float* row = attn_out + (((size_t)(b * H_ + h) * T_ + i) * T_);
        for (int j = l8; j < T_; j += 8) {
            float v = 0.f;
            if (j >= jlo && j <= i) v = Sc[qr][j - jlo];
            row[j] = v;
        }
    }

    // ---- PV: out[qr, d0..d0+7] = sum_j w * V[j, :] ----
    const int d0 = l8 * 8;
    float acc[8];
#pragma unroll
    for (int dd = 0; dd < 8; dd++) acc[dd] = 0.f;

    for (int c0 = 0; c0 < nk; c0 += QT) {
        __syncthreads();
        {   // load V chunk
            const float* src = V + (size_t)(b * T_ + jlo + c0 + qr) * D_ + h * HD_ + l8 * 8;
            float4 v0 = *(const float4*)(src);
            float4 v1 = *(const float4*)(src + 4);
            KVs[qr][l8 * 8 + 0] = v0.x; KVs[qr][l8 * 8 + 1] = v0.y;
            KVs[qr][l8 * 8 + 2] = v0.z; KVs[qr][l8 * 8 + 3] = v0.w;
            KVs[qr][l8 * 8 + 4] = v1.x; KVs[qr][l8 * 8 + 5] = v1.y;
            KVs[qr][l8 * 8 + 6] = v1.z; KVs[qr][l8 * 8 + 7] = v1.w;
        }
        __syncthreads();

        for (int jj = 0; jj < QT; jj++) {
            float w = Sc[qr][c0 + jj];
#pragma unroll
            for (int dd = 0; dd < 8; dd++)
                acc[dd] += w * KVs[jj][d0 + dd];
        }
    }

    float* p = P + (size_t)(b * T_ + i) * D_ + h * HD_ + d0;
#pragma unroll
    for (int dd = 0; dd < 8; dd++) p[dd] = acc[dd];
}

// ---------------------------------------------------------------------------
extern "C" void kernel_launch(void* const* d_in, const int* in_sizes, int n_in,
                              void* d_out, int out_size)
{
    const float* x  = (const float*)d_in[0];
    const float* Wq = (const float*)d_in[1];
    const float* bq = (const float*)d_in[2];
    const float* Wk = (const float*)d_in[3];
    const float* bk = (const float*)d_in[4];
    const float* Wv = (const float*)d_in[5];
    const float* bv = (const float*)d_in[6];
    const float* Wo = (const float*)d_in[7];
    const float* bo = (const float*)d_in[8];
    float* out = (float*)d_out;

    const int has_attn = ((size_t)out_size >= OUT_ELEMS + ATTN_ELEMS) ? 1 : 0;

    float *pQ, *pK, *pV, *pP;
    cudaGetSymbolAddress((void**)&pQ, g_Q);
    cudaGetSymbolAddress((void**)&pK, g_K);
    cudaGetSymbolAddress((void**)&pV, g_V);
    cudaGetSymbolAddress((void**)&pP, g_P);

    dim3 ggrid(D_ / 64, MROWS / 64);  // (16, 64)
    sgemm_nt_bias<<<ggrid, 256>>>(x, Wq, bq, pQ, MROWS, D_, D_);
    sgemm_nt_bias<<<ggrid, 256>>>(x, Wk, bk, pK, MROWS, D_, D_);
    sgemm_nt_bias<<<ggrid, 256>>>(x, Wv, bv, pV, MROWS, D_, D_);

    dim3 agrid(T_ / QT, H_, B_);      // (64, 16, 2)
    attn_banded_kernel<<<agrid, 256>>>(pQ, pK, pV, pP,
                                       has_attn ? (out + OUT_ELEMS) : out,
                                       has_attn);

    sgemm_nt_bias<<<ggrid, 256>>>(pP, Wo, bo, out, MROWS, D_, D_);
}

// round 5
// speedup vs baseline: 1.9670x; 1.9670x over previous
#include <cuda_runtime.h>
#include <cuda_bf16.h>
#include <math.h>
#include <stdint.h>

// ---------------------------------------------------------------------------
// ALiBi self-attention. B=2, T=2048, D=1024, H=16, hd=64.
// Toolchain compiles for base sm_100 (no 'a' suffix) => tcgen05 unavailable.
// Tensor path = baseline mma.sync m16n8k16 bf16 (HMMA) + ldmatrix + cp.async.
//  * 4 projection GEMMs: bf16 hi/lo split, K expanded 1024->3072:
//      A3 row = [hi(A) | hi(A) | lo(A)],  W3 row = [hi(W) | lo(W) | hi(W)]
//      => one bf16 GEMM over K=3072 computes ah*bh + ah*bl + al*bh (~1e-5 rel)
//  * Banded attention (ALiBi slope 1 + causal => exact fp32 underflow beyond
//    distance ~190; band = 192 back + 32 tile), float4-vectorized.
// ---------------------------------------------------------------------------

#define B_    2
#define T_    2048
#define D_    1024
#define H_    16
#define HD_   64
#define MROWS 4096
#define KE    3072
#define NCH   48                     // K chunks of 64 bf16
#define OUT_ELEMS  ((size_t)MROWS * D_)
#define ATTN_ELEMS ((size_t)B_ * H_ * T_ * T_)

#define QT    32
#define WBACK 192

// ---------------- device scratch (allocation-free rule) --------------------
__device__ __align__(256) float g_Q[MROWS * D_];
__device__ __align__(256) float g_K[MROWS * D_];
__device__ __align__(256) float g_V[MROWS * D_];
__device__ __align__(256) float g_P[MROWS * D_];
__device__ __align__(256) __nv_bfloat16 g_A3[(size_t)MROWS * KE];
__device__ __align__(256) __nv_bfloat16 g_P3[(size_t)MROWS * KE];
__device__ __align__(256) __nv_bfloat16 g_W3[4][(size_t)D_ * KE];

// ---------------- PTX helpers (all baseline sm_80-level) --------------------
__device__ __forceinline__ uint32_t s2u(const void* p) {
    uint32_t a;
    asm("{ .reg .u64 t; cvta.to.shared.u64 t, %1; cvt.u32.u64 %0, t; }"
        : "=r"(a) : "l"(p));
    return a;
}

__device__ __forceinline__ void cp16(uint32_t dst, const void* src) {
    asm volatile("cp.async.cg.shared.global [%0], [%1], 16;"
                 :: "r"(dst), "l"(src) : "memory");
}
#define CP_COMMIT() asm volatile("cp.async.commit_group;" ::: "memory")
#define CP_WAIT(n)  asm volatile("cp.async.wait_group %0;" :: "n"(n) : "memory")

__device__ __forceinline__ void ldsm4(uint32_t* r, uint32_t addr) {
    asm volatile("ldmatrix.sync.aligned.m8n8.x4.shared.b16 {%0,%1,%2,%3}, [%4];"
                 : "=r"(r[0]), "=r"(r[1]), "=r"(r[2]), "=r"(r[3]) : "r"(addr));
}

__device__ __forceinline__ void mma16816(float* c, const uint32_t* a,
                                         uint32_t b0, uint32_t b1) {
    asm volatile(
        "mma.sync.aligned.m16n8k16.row.col.f32.bf16.bf16.f32 "
        "{%0,%1,%2,%3}, {%4,%5,%6,%7}, {%8,%9}, {%0,%1,%2,%3};"
        : "+f"(c[0]), "+f"(c[1]), "+f"(c[2]), "+f"(c[3])
        : "r"(a[0]), "r"(a[1]), "r"(a[2]), "r"(a[3]), "r"(b0), "r"(b1));
}

// ---------------------------------------------------------------------------
// hi/lo split conversion: in fp32 [rows,1024] -> out bf16 [rows,3072]
// ---------------------------------------------------------------------------
__global__ void __launch_bounds__(256) cvt3(const float* __restrict__ in,
                                            __nv_bfloat16* __restrict__ out,
                                            int n, int loMask) {
    int i = blockIdx.x * 256 + threadIdx.x;
    if (i >= n) return;
    float v = in[i];
    __nv_bfloat16 h = __float2bfloat16(v);
    __nv_bfloat16 l = __float2bfloat16(v - __bfloat162float(h));
    int r = i >> 10, k = i & 1023;
    __nv_bfloat16* o = out + (size_t)r * KE + k;
    o[0]    = (loMask & 1) ? l : h;
    o[1024] = (loMask & 2) ? l : h;
    o[2048] = (loMask & 4) ? l : h;
}

// ---------------------------------------------------------------------------
// HMMA bf16 GEMM: C[4096,1024] = A3[4096,KE] @ B3[1024,KE]^T + bias.
// CTA 128x128, 8 warps (2x4), warp tile 64x32 (4x4 m16n8k16 atoms).
// BK=64 bf16 (128B) per chunk, smem rows padded to 144B (conflict-free
// ldmatrix: bank group of row r = 4r mod 32, distinct for r mod 8).
// cp.async double buffer: load chunk c+1 while computing chunk c.
// ---------------------------------------------------------------------------
#define ROWB     144                 // padded smem row stride (bytes)
#define TILEB    (128 * ROWB)        // 18432 B per operand tile
#define STAGEB   (2 * TILEB)         // A + B one stage
#define GSMEM    (2 * STAGEB)        // 73728 B double buffered

__global__ void __launch_bounds__(256) gemm_hmma(
    const __nv_bfloat16* __restrict__ A3, const __nv_bfloat16* __restrict__ B3,
    const float* __restrict__ bias, float* __restrict__ C) {
    extern __shared__ __align__(128) char smem[];
    const uint32_t sb = s2u(smem);
    const int tid  = threadIdx.x;
    const int lane = tid & 31;
    const int w    = tid >> 5;
    const int wm   = (w & 1) * 64;       // warp M offset in CTA tile
    const int wn   = (w >> 1) * 32;      // warp N offset
    const int bm   = blockIdx.y * 128;
    const int bn   = blockIdx.x * 128;

    float acc[4][4][4];
#pragma unroll
    for (int i = 0; i < 4; i++)
#pragma unroll
        for (int j = 0; j < 4; j++)
#pragma unroll
            for (int q = 0; q < 4; q++) acc[i][j][q] = 0.f;

    // per-thread cp.async assignments: 1024 16B units per operand tile,
    // 256 threads x 4 units; unit u: row=u>>3, col16=u&7.
    const char* gAbase = (const char*)A3 + (size_t)bm * (KE * 2);
    const char* gBbase = (const char*)B3 + (size_t)bn * (KE * 2);

#define LOAD_STAGE(c, s)                                                      \
    do {                                                                      \
        uint32_t dA = sb + (s) * STAGEB;                                      \
        uint32_t dB = dA + TILEB;                                             \
        const char* sA = gAbase + (c) * 128;                                  \
        const char* sB = gBbase + (c) * 128;                                  \
        _Pragma("unroll")                                                     \
        for (int it = 0; it < 4; it++) {                                      \
            int u = tid + it * 256;                                           \
            int r = u >> 3, q = (u & 7) << 4;                                 \
            cp16(dA + r * ROWB + q, sA + (size_t)r * (KE * 2) + q);           \
            cp16(dB + r * ROWB + q, sB + (size_t)r * (KE * 2) + q);           \
        }                                                                     \
        CP_COMMIT();                                                          \
    } while (0)

    LOAD_STAGE(0, 0);

    for (int c = 0; c < NCH; c++) {
        const int s = c & 1;
        if (c + 1 < NCH) { LOAD_STAGE(c + 1, s ^ 1); CP_WAIT(1); }
        else             { CP_WAIT(0); }
        __syncthreads();

        // ldmatrix lane addressing: row = tileRow + (lane&15), col16 = lane>>4
        const uint32_t aBase = sb + s * STAGEB +
                               (wm + (lane & 15)) * ROWB + ((lane >> 4) << 4);
        const uint32_t bBase = sb + s * STAGEB + TILEB +
                               (wn + (lane & 15)) * ROWB + ((lane >> 4) << 4);
#pragma unroll
        for (int kk = 0; kk < 4; kk++) {       // 4 k16 steps per 64-wide chunk
            uint32_t af[4][4], bf[2][4];
#pragma unroll
            for (int i = 0; i < 4; i++)
                ldsm4(af[i], aBase + i * 16 * ROWB + kk * 32);
#pragma unroll
            for (int p = 0; p < 2; p++)
                ldsm4(bf[p], bBase + p * 16 * ROWB + kk * 32);
            // n-atom j: pair p=j>>1, half h=j&1: b0=bf[p][h], b1=bf[p][h+2]
#pragma unroll
            for (int i = 0; i < 4; i++)
#pragma unroll
                for (int j = 0; j < 4; j++)
                    mma16816(acc[i][j], af[i], bf[j >> 1][j & 1],
                             bf[j >> 1][(j & 1) + 2]);
        }
        __syncthreads();
    }

    // epilogue: c0,c1 = C[g][2t,2t+1], c2,c3 = C[g+8][2t,2t+1]
    const int g = lane >> 2, tg = lane & 3;
#pragma unroll
    for (int i = 0; i < 4; i++) {
#pragma unroll
        for (int j = 0; j < 4; j++) {
            int col  = bn + wn + j * 8 + tg * 2;
            float b0 = bias[col], b1 = bias[col + 1];
            int row0 = bm + wm + i * 16 + g;
            float2 v0 = make_float2(acc[i][j][0] + b0, acc[i][j][1] + b1);
            float2 v1 = make_float2(acc[i][j][2] + b0, acc[i][j][3] + b1);
            *(float2*)&C[(size_t)row0 * D_ + col]       = v0;
            *(float2*)&C[(size_t)(row0 + 8) * D_ + col] = v1;
        }
    }
}

// ---------------------------------------------------------------------------
// Banded attention, vectorized. Grid (T/32, H, B), 256 threads.
// ---------------------------------------------------------------------------
__global__ void __launch_bounds__(256) attn2(
    const float* __restrict__ Q, const float* __restrict__ K,
    const float* __restrict__ V, float* __restrict__ P,
    float* __restrict__ attn_out, int has_attn) {
    __shared__ float Qs[QT][68];
    __shared__ float KV[2304];      // union: Kt[64][36] (QK) / Vs[32][68] (PV)
    __shared__ float Sc[QT][228];

    const int b = blockIdx.z, h = blockIdx.y;
    const int q0 = blockIdx.x * QT;
    const int tid = threadIdx.x;
    const int qr = tid >> 3, l8 = tid & 7;
    const int jlo = (q0 > WBACK) ? q0 - WBACK : 0;
    const int nk = q0 + QT - jlo;   // multiple of 32, <= 224

    {   // Q tile [32 x 64]
        const float* src = Q + (size_t)(b * T_ + q0 + qr) * D_ + h * HD_ + l8 * 8;
        float4 v0 = ((const float4*)src)[0], v1 = ((const float4*)src)[1];
        *(float4*)&Qs[qr][l8 * 8] = v0;
        *(float4*)&Qs[qr][l8 * 8 + 4] = v1;
    }

    // ---- QK over band, K chunk transposed in smem ----
    const int jb = l8 * 4;
    for (int c0 = 0; c0 < nk; c0 += QT) {
        __syncthreads();
        {
            const float* src = K + (size_t)(b * T_ + jlo + c0 + qr) * D_ + h * HD_ + l8 * 8;
            float4 v0 = ((const float4*)src)[0], v1 = ((const float4*)src)[1];
            int d0 = l8 * 8;
            KV[(d0 + 0) * 36 + qr] = v0.x; KV[(d0 + 1) * 36 + qr] = v0.y;
            KV[(d0 + 2) * 36 + qr] = v0.z; KV[(d0 + 3) * 36 + qr] = v0.w;
            KV[(d0 + 4) * 36 + qr] = v1.x; KV[(d0 + 5) * 36 + qr] = v1.y;
            KV[(d0 + 6) * 36 + qr] = v1.z; KV[(d0 + 7) * 36 + qr] = v1.w;
        }
        __syncthreads();

        float4 s = make_float4(0.f, 0.f, 0.f, 0.f);
#pragma unroll
        for (int d4 = 0; d4 < 16; d4++) {
            float4 qa = *(const float4*)&Qs[qr][d4 * 4];
            float4 k0 = *(const float4*)&KV[(d4 * 4 + 0) * 36 + jb];
            float4 k1 = *(const float4*)&KV[(d4 * 4 + 1) * 36 + jb];
            float4 k2 = *(const float4*)&KV[(d4 * 4 + 2) * 36 + jb];
            float4 k3 = *(const float4*)&KV[(d4 * 4 + 3) * 36 + jb];
            s.x += qa.x * k0.x + qa.y * k1.x + qa.z * k2.x + qa.w * k3.x;
            s.y += qa.x * k0.y + qa.y * k1.y + qa.z * k2.y + qa.w * k3.y;
            s.z += qa.x * k0.z + qa.y * k1.z + qa.z * k2.z + qa.w * k3.z;
            s.w += qa.x * k0.w + qa.y * k1.w + qa.z * k2.w + qa.w * k3.w;
        }
        Sc[qr][c0 + jb + 0] = s.x * 0.125f;
        Sc[qr][c0 + jb + 1] = s.y * 0.125f;
        Sc[qr][c0 + jb + 2] = s.z * 0.125f;
        Sc[qr][c0 + jb + 3] = s.w * 0.125f;
    }
    __syncthreads();

    // ---- softmax per query row (8 lanes cooperate) ----
    const int i = q0 + qr;
    float m = -1e30f;
    for (int idx = l8; idx < nk; idx += 8) {
        int j = jlo + idx;
        float sv = (j <= i) ? (Sc[qr][idx] - (float)(i - j)) : -1e30f;
        Sc[qr][idx] = sv;
        m = fmaxf(m, sv);
    }
#pragma unroll
    for (int o = 4; o >= 1; o >>= 1)
        m = fmaxf(m, __shfl_xor_sync(0xffffffffu, m, o, 8));

    float sum = 0.f;
    for (int idx = l8; idx < nk; idx += 8) {
        float sv = Sc[qr][idx];
        float e = (sv > -1e29f) ? expf(sv - m) : 0.f;
        Sc[qr][idx] = e;
        sum += e;
    }
#pragma unroll
    for (int o = 4; o >= 1; o >>= 1)
        sum += __shfl_xor_sync(0xffffffffu, sum, o, 8);
    float inv = 1.f / sum;
    for (int idx = l8; idx < nk; idx += 8)
        Sc[qr][idx] *= inv;
    __syncthreads();

    // ---- full attn row, float4-coalesced (zeros outside band) ----
    if (has_attn) {
        float* row = attn_out + ((size_t)(b * H_ + h) * T_ + i) * T_;
        for (int j4 = l8; j4 < T_ / 4; j4 += 8) {
            int j = j4 * 4;
            float4 v = make_float4(0.f, 0.f, 0.f, 0.f);
            if (j + 3 >= jlo && j <= i) {
                int lo = j - jlo;
                v.x = (j + 0 >= jlo && j + 0 <= i) ? Sc[qr][lo + 0] : 0.f;
                v.y = (j + 1 >= jlo && j + 1 <= i) ? Sc[qr][lo + 1] : 0.f;
                v.z = (j + 2 >= jlo && j + 2 <= i) ? Sc[qr][lo + 2] : 0.f;
                v.w = (j + 3 >= jlo && j + 3 <= i) ? Sc[qr][lo + 3] : 0.f;
            }
            *(float4*)(row + j) = v;
        }
    }

    // ---- PV: out[qr][d0..d0+7] ----
    const int d0 = l8 * 8;
    float4 a0 = make_float4(0.f, 0.f, 0.f, 0.f);
    float4 a1 = make_float4(0.f, 0.f, 0.f, 0.f);
    for (int c0 = 0; c0 < nk; c0 += QT) {
        __syncthreads();
        {
            const float* src = V + (size_t)(b * T_ + jlo + c0 + qr) * D_ + h * HD_ + l8 * 8;
            float4 v0 = ((const float4*)src)[0], v1 = ((const float4*)src)[1];
            *(float4*)&KV[qr * 68 + l8 * 8] = v0;
            *(float4*)&KV[qr * 68 + l8 * 8 + 4] = v1;
        }
        __syncthreads();
#pragma unroll
        for (int jj = 0; jj < QT; jj++) {
            float w = Sc[qr][c0 + jj];
            float4 v0 = *(const float4*)&KV[jj * 68 + d0];
            float4 v1 = *(const float4*)&KV[jj * 68 + d0 + 4];
            a0.x += w * v0.x; a0.y += w * v0.y; a0.z += w * v0.z; a0.w += w * v0.w;
            a1.x += w * v1.x; a1.y += w * v1.y; a1.z += w * v1.z; a1.w += w * v1.w;
        }
    }
    float* p = P + (size_t)(b * T_ + i) * D_ + h * HD_ + d0;
    ((float4*)p)[0] = a0;
    ((float4*)p)[1] = a1;
}

// ---------------------------------------------------------------------------
extern "C" void kernel_launch(void* const* d_in, const int* in_sizes, int n_in,
                              void* d_out, int out_size) {
    const float* x  = (const float*)d_in[0];
    const float* Wq = (const float*)d_in[1];
    const float* bq = (const float*)d_in[2];
    const float* Wk = (const float*)d_in[3];
    const float* bk = (const float*)d_in[4];
    const float* Wv = (const float*)d_in[5];
    const float* bv = (const float*)d_in[6];
    const float* Wo = (const float*)d_in[7];
    const float* bo = (const float*)d_in[8];
    float* out = (float*)d_out;

    const int has_attn = ((size_t)out_size >= OUT_ELEMS + ATTN_ELEMS) ? 1 : 0;

    float *pQ, *pK, *pV, *pP;
    __nv_bfloat16 *pA3, *pP3, *pW3;
    cudaGetSymbolAddress((void**)&pQ, g_Q);
    cudaGetSymbolAddress((void**)&pK, g_K);
    cudaGetSymbolAddress((void**)&pV, g_V);
    cudaGetSymbolAddress((void**)&pP, g_P);
    cudaGetSymbolAddress((void**)&pA3, g_A3);
    cudaGetSymbolAddress((void**)&pP3, g_P3);
    cudaGetSymbolAddress((void**)&pW3, g_W3);

    cudaFuncSetAttribute(gemm_hmma, cudaFuncAttributeMaxDynamicSharedMemorySize,
                         GSMEM);

    const int nA = MROWS * D_;
    const int nW = D_ * D_;
    cvt3<<<(nA + 255) / 256, 256>>>(x, pA3, nA, 4);                       // [h|h|l]
    cvt3<<<(nW + 255) / 256, 256>>>(Wq, pW3 + 0 * (size_t)D_ * KE, nW, 2); // [h|l|h]
    cvt3<<<(nW + 255) / 256, 256>>>(Wk, pW3 + 1 * (size_t)D_ * KE, nW, 2);
    cvt3<<<(nW + 255) / 256, 256>>>(Wv, pW3 + 2 * (size_t)D_ * KE, nW, 2);
    cvt3<<<(nW + 255) / 256, 256>>>(Wo, pW3 + 3 * (size_t)D_ * KE, nW, 2);

    dim3 gg(D_ / 128, MROWS / 128);   // (8, 32)
    gemm_hmma<<<gg, 256, GSMEM>>>(pA3, pW3 + 0 * (size_t)D_ * KE, bq, pQ);
    gemm_hmma<<<gg, 256, GSMEM>>>(pA3, pW3 + 1 * (size_t)D_ * KE, bk, pK);
    gemm_hmma<<<gg, 256, GSMEM>>>(pA3, pW3 + 2 * (size_t)D_ * KE, bv, pV);

    dim3 agrid(T_ / QT, H_, B_);      // (64, 16, 2)
    attn2<<<agrid, 256>>>(pQ, pK, pV, pP,
                          has_attn ? (out + OUT_ELEMS) : out, has_attn);

    cvt3<<<(nA + 255) / 256, 256>>>(pP, pP3, nA, 4);
    gemm_hmma<<<gg, 256, GSMEM>>>(pP3, pW3 + 3 * (size_t)D_ * KE, bo, out);
}

// round 7
// speedup vs baseline: 2.0748x; 1.0548x over previous
#include <cuda_runtime.h>
#include <cuda_bf16.h>
#include <math.h>
#include <stdint.h>

// ---------------------------------------------------------------------------
// ALiBi self-attention. B=2, T=2048, D=1024, H=16, hd=64.
// sm_100 baseline (no tcgen05): mma.sync m16n8k16 bf16 + ldmatrix + cp.async.
//  * QKV fused into ONE GEMM: W3[0..2] contiguous => weight [3072, KE].
//  * bf16 hi/lo split, K expanded 1024->3072 (err ~1.4e-5, threshold 1e-3).
//  * __launch_bounds__(256,2): 2 CTAs/SM (round-5 bottleneck was 1 CTA/SM).
//  * Banded attention (exact fp32 underflow beyond distance ~190).
// ---------------------------------------------------------------------------

#define B_    2
#define T_    2048
#define D_    1024
#define H_    16
#define HD_   64
#define MROWS 4096
#define KE    3072
#define NCH   48                     // K chunks of 64 bf16
#define OUT_ELEMS  ((size_t)MROWS * D_)
#define ATTN_ELEMS ((size_t)B_ * H_ * T_ * T_)

#define QT    32
#define WBACK 192

// ---------------- device scratch (allocation-free rule) --------------------
__device__ __align__(256) float g_Q[MROWS * D_];
__device__ __align__(256) float g_K[MROWS * D_];
__device__ __align__(256) float g_V[MROWS * D_];
__device__ __align__(256) float g_P[MROWS * D_];
__device__ __align__(256) __nv_bfloat16 g_A3[(size_t)MROWS * KE];
__device__ __align__(256) __nv_bfloat16 g_P3[(size_t)MROWS * KE];
__device__ __align__(256) __nv_bfloat16 g_W3[4][(size_t)D_ * KE];

// ---------------- PTX helpers (baseline sm_80-level) ------------------------
__device__ __forceinline__ uint32_t s2u(const void* p) {
    uint32_t a;
    asm("{ .reg .u64 t; cvta.to.shared.u64 t, %1; cvt.u32.u64 %0, t; }"
        : "=r"(a) : "l"(p));
    return a;
}

__device__ __forceinline__ void cp16(uint32_t dst, const void* src) {
    asm volatile("cp.async.cg.shared.global [%0], [%1], 16;"
                 :: "r"(dst), "l"(src) : "memory");
}
#define CP_COMMIT() asm volatile("cp.async.commit_group;" ::: "memory")
#define CP_WAIT(n)  asm volatile("cp.async.wait_group %0;" :: "n"(n) : "memory")

__device__ __forceinline__ void ldsm4(uint32_t* r, uint32_t addr) {
    asm volatile("ldmatrix.sync.aligned.m8n8.x4.shared.b16 {%0,%1,%2,%3}, [%4];"
                 : "=r"(r[0]), "=r"(r[1]), "=r"(r[2]), "=r"(r[3]) : "r"(addr));
}

__device__ __forceinline__ void mma16816(float* c, const uint32_t* a,
                                         uint32_t b0, uint32_t b1) {
    asm volatile(
        "mma.sync.aligned.m16n8k16.row.col.f32.bf16.bf16.f32 "
        "{%0,%1,%2,%3}, {%4,%5,%6,%7}, {%8,%9}, {%0,%1,%2,%3};"
        : "+f"(c[0]), "+f"(c[1]), "+f"(c[2]), "+f"(c[3])
        : "r"(a[0]), "r"(a[1]), "r"(a[2]), "r"(a[3]), "r"(b0), "r"(b1));
}

// ---------------------------------------------------------------------------
// hi/lo split, vectorized 4 elems/thread: fp32 [rows,1024] -> bf16 [rows,3072]
// block b of output row = hi or lo per loMask bit b.
// ---------------------------------------------------------------------------
__global__ void __launch_bounds__(256) cvt3v(const float* __restrict__ in,
                                             __nv_bfloat16* __restrict__ out,
                                             int n4, int loMask) {
    int i = blockIdx.x * 256 + threadIdx.x;
    if (i >= n4) return;
    float4 v = ((const float4*)in)[i];
    __nv_bfloat162 h01 = __floats2bfloat162_rn(v.x, v.y);
    __nv_bfloat162 h23 = __floats2bfloat162_rn(v.z, v.w);
    __nv_bfloat162 l01 = __floats2bfloat162_rn(v.x - __bfloat162float(h01.x),
                                               v.y - __bfloat162float(h01.y));
    __nv_bfloat162 l23 = __floats2bfloat162_rn(v.z - __bfloat162float(h23.x),
                                               v.w - __bfloat162float(h23.y));
    uint32_t h0 = *(uint32_t*)&h01, h1 = *(uint32_t*)&h23;
    uint32_t l0 = *(uint32_t*)&l01, l1 = *(uint32_t*)&l23;
    int idx = i * 4;
    int r = idx >> 10, k = idx & 1023;
    uint32_t* o = (uint32_t*)(out + (size_t)r * KE + k);
    o[0]    = (loMask & 1) ? l0 : h0;  o[1]    = (loMask & 1) ? l1 : h1;
    o[512]  = (loMask & 2) ? l0 : h0;  o[513]  = (loMask & 2) ? l1 : h1;  // +1024
    o[1024] = (loMask & 4) ? l0 : h0;  o[1025] = (loMask & 4) ? l1 : h1;  // +2048
}

// ---------------------------------------------------------------------------
// HMMA bf16 GEMM: C = A3 @ B3^T + bias. B3 rows = 3072 (fused QKV) or 1024.
// Output tile routed by bn>>10 to out0/1/2. CTA 128x128, 8 warps (2x4),
// warp tile 64x32. BK=64, smem rows 144B, cp.async double buffer, 2 CTAs/SM.
// ---------------------------------------------------------------------------
#define ROWB     144
#define TILEB    (128 * ROWB)        // 18432 B
#define STAGEB   (2 * TILEB)
#define GSMEM    (2 * STAGEB)        // 73728 B

__global__ void __launch_bounds__(256, 2) gemm_hmma(
    const __nv_bfloat16* __restrict__ A3, const __nv_bfloat16* __restrict__ B3,
    const float* __restrict__ bias0, const float* __restrict__ bias1,
    const float* __restrict__ bias2,
    float* __restrict__ out0, float* __restrict__ out1, float* __restrict__ out2) {
    extern __shared__ __align__(128) char smem[];
    const uint32_t sb = s2u(smem);
    const int tid  = threadIdx.x;
    const int lane = tid & 31;
    const int w    = tid >> 5;
    const int wm   = (w & 1) * 64;
    const int wn   = (w >> 1) * 32;
    const int bm   = blockIdx.y * 128;
    const int bn   = blockIdx.x * 128;

    const int mat = bn >> 10;
    const float* bias = (mat == 0) ? bias0 : (mat == 1) ? bias1 : bias2;
    float* C          = (mat == 0) ? out0  : (mat == 1) ? out1  : out2;
    const int cn = bn & 1023;

    float acc[4][4][4];
#pragma unroll
    for (int i = 0; i < 4; i++)
#pragma unroll
        for (int j = 0; j < 4; j++)
#pragma unroll
            for (int q = 0; q < 4; q++) acc[i][j][q] = 0.f;

    const char* gAbase = (const char*)A3 + (size_t)bm * (KE * 2);
    const char* gBbase = (const char*)B3 + (size_t)bn * (KE * 2);

#define LOAD_STAGE(c, s)                                                      \
    do {                                                                      \
        uint32_t dA = sb + (s) * STAGEB;                                      \
        uint32_t dB = dA + TILEB;                                             \
        const char* sA = gAbase + (c) * 128;                                  \
        const char* sB = gBbase + (c) * 128;                                  \
        _Pragma("unroll")                                                     \
        for (int it = 0; it < 4; it++) {                                      \
            int u = tid + it * 256;                                           \
            int r = u >> 3, q = (u & 7) << 4;                                 \
            cp16(dA + r * ROWB + q, sA + (size_t)r * (KE * 2) + q);           \
            cp16(dB + r * ROWB + q, sB + (size_t)r * (KE * 2) + q);           \
        }                                                                     \
        CP_COMMIT();                                                          \
    } while (0)

    LOAD_STAGE(0, 0);

    for (int c = 0; c < NCH; c++) {
        const int s = c & 1;
        if (c + 1 < NCH) { LOAD_STAGE(c + 1, s ^ 1); CP_WAIT(1); }
        else             { CP_WAIT(0); }
        __syncthreads();

        const uint32_t aBase = sb + s * STAGEB +
                               (wm + (lane & 15)) * ROWB + ((lane >> 4) << 4);
        const uint32_t bBase = sb + s * STAGEB + TILEB +
                               (wn + (lane & 15)) * ROWB + ((lane >> 4) << 4);
#pragma unroll
        for (int kk = 0; kk < 4; kk++) {
            uint32_t af[4][4], bf[2][4];
#pragma unroll
            for (int i = 0; i < 4; i++)
                ldsm4(af[i], aBase + i * 16 * ROWB + kk * 32);
#pragma unroll
            for (int p = 0; p < 2; p++)
                ldsm4(bf[p], bBase + p * 16 * ROWB + kk * 32);
#pragma unroll
            for (int i = 0; i < 4; i++)
#pragma unroll
                for (int j = 0; j < 4; j++)
                    mma16816(acc[i][j], af[i], bf[j >> 1][j & 1],
                             bf[j >> 1][(j & 1) + 2]);
        }
        __syncthreads();
    }

    const int g = lane >> 2, tg = lane & 3;
#pragma unroll
    for (int i = 0; i < 4; i++) {
#pragma unroll
        for (int j = 0; j < 4; j++) {
            int col  = cn + wn + j * 8 + tg * 2;
            float b0 = bias[col], b1 = bias[col + 1];
            int row0 = bm + wm + i * 16 + g;
            float2 v0 = make_float2(acc[i][j][0] + b0, acc[i][j][1] + b1);
            float2 v1 = make_float2(acc[i][j][2] + b0, acc[i][j][3] + b1);
            *(float2*)&C[(size_t)row0 * D_ + col]       = v0;
            *(float2*)&C[(size_t)(row0 + 8) * D_ + col] = v1;
        }
    }
}

// ---------------------------------------------------------------------------
// Banded attention, vectorized. Grid (T/32, H, B), 256 threads.
// ---------------------------------------------------------------------------
__global__ void __launch_bounds__(256) attn2(
    const float* __restrict__ Q, const float* __restrict__ K,
    const float* __restrict__ V, float* __restrict__ P,
    float* __restrict__ attn_out, int has_attn) {
    __shared__ float Qs[QT][68];
    __shared__ float KV[2304];
    __shared__ float Sc[QT][228];

    const int b = blockIdx.z, h = blockIdx.y;
    const int q0 = blockIdx.x * QT;
    const int tid = threadIdx.x;
    const int qr = tid >> 3, l8 = tid & 7;
    const int jlo = (q0 > WBACK) ? q0 - WBACK : 0;
    const int nk = q0 + QT - jlo;

    {
        const float* src = Q + (size_t)(b * T_ + q0 + qr) * D_ + h * HD_ + l8 * 8;
        float4 v0 = ((const float4*)src)[0], v1 = ((const float4*)src)[1];
        *(float4*)&Qs[qr][l8 * 8] = v0;
        *(float4*)&Qs[qr][l8 * 8 + 4] = v1;
    }

    const int jb = l8 * 4;
    for (int c0 = 0; c0 < nk; c0 += QT) {
        __syncthreads();
        {
            const float* src = K + (size_t)(b * T_ + jlo + c0 + qr) * D_ + h * HD_ + l8 * 8;
            float4 v0 = ((const float4*)src)[0], v1 = ((const float4*)src)[1];
            int d0 = l8 * 8;
            KV[(d0 + 0) * 36 + qr] = v0.x; KV[(d0 + 1) * 36 + qr] = v0.y;
            KV[(d0 + 2) * 36 + qr] = v0.z; KV[(d0 + 3) * 36 + qr] = v0.w;
            KV[(d0 + 4) * 36 + qr] = v1.x; KV[(d0 + 5) * 36 + qr] = v1.y;
            KV[(d0 + 6) * 36 + qr] = v1.z; KV[(d0 + 7) * 36 + qr] = v1.w;
        }
        __syncthreads();

        float4 s = make_float4(0.f, 0.f, 0.f, 0.f);
#pragma unroll
        for (int d4 = 0; d4 < 16; d4++) {
            float4 qa = *(const float4*)&Qs[qr][d4 * 4];
            float4 k0 = *(const float4*)&KV[(d4 * 4 + 0) * 36 + jb];
            float4 k1 = *(const float4*)&KV[(d4 * 4 + 1) * 36 + jb];
            float4 k2 = *(const float4*)&KV[(d4 * 4 + 2) * 36 + jb];
            float4 k3 = *(const float4*)&KV[(d4 * 4 + 3) * 36 + jb];
            s.x += qa.x * k0.x + qa.y * k1.x + qa.z * k2.x + qa.w * k3.x;
            s.y += qa.x * k0.y + qa.y * k1.y + qa.z * k2.y + qa.w * k3.y;
            s.z += qa.x * k0.z + qa.y * k1.z + qa.z * k2.z + qa.w * k3.z;
            s.w += qa.x * k0.w + qa.y * k1.w + qa.z * k2.w + qa.w * k3.w;
        }
        Sc[qr][c0 + jb + 0] = s.x * 0.125f;
        Sc[qr][c0 + jb + 1] = s.y * 0.125f;
        Sc[qr][c0 + jb + 2] = s.z * 0.125f;
        Sc[qr][c0 + jb + 3] = s.w * 0.125f;
    }
    __syncthreads();

    const int i = q0 + qr;
    float m = -1e30f;
    for (int idx = l8; idx < nk; idx += 8) {
        int j = jlo + idx;
        float sv = (j <= i) ? (Sc[qr][idx] - (float)(i - j)) : -1e30f;
        Sc[qr][idx] = sv;
        m = fmaxf(m, sv);
    }
#pragma unroll
    for (int o = 4; o >= 1; o >>= 1)
        m = fmaxf(m, __shfl_xor_sync(0xffffffffu, m, o, 8));

    float sum = 0.f;
    for (int idx = l8; idx < nk; idx += 8) {
        float sv = Sc[qr][idx];
        float e = (sv > -1e29f) ? expf(sv - m) : 0.f;
        Sc[qr][idx] = e;
        sum += e;
    }
#pragma unroll
    for (int o = 4; o >= 1; o >>= 1)
        sum += __shfl_xor_sync(0xffffffffu, sum, o, 8);
    float inv = 1.f / sum;
    for (int idx = l8; idx < nk; idx += 8)
        Sc[qr][idx] *= inv;
    __syncthreads();

    if (has_attn) {
        float* row = attn_out + ((size_t)(b * H_ + h) * T_ + i) * T_;
        for (int j4 = l8; j4 < T_ / 4; j4 += 8) {
            int j = j4 * 4;
            float4 v = make_float4(0.f, 0.f, 0.f, 0.f);
            if (j + 3 >= jlo && j <= i) {
                int lo = j - jlo;
                v.x = (j + 0 >= jlo && j + 0 <= i) ? Sc[qr][lo + 0] : 0.f;
                v.y = (j + 1 >= jlo && j + 1 <= i) ? Sc[qr][lo + 1] : 0.f;
                v.z = (j + 2 >= jlo && j + 2 <= i) ? Sc[qr][lo + 2] : 0.f;
                v.w = (j + 3 >= jlo && j + 3 <= i) ? Sc[qr][lo + 3] : 0.f;
            }
            *(float4*)(row + j) = v;
        }
    }

    const int d0 = l8 * 8;
    float4 a0 = make_float4(0.f, 0.f, 0.f, 0.f);
    float4 a1 = make_float4(0.f, 0.f, 0.f, 0.f);
    for (int c0 = 0; c0 < nk; c0 += QT) {
        __syncthreads();
        {
            const float* src = V + (size_t)(b * T_ + jlo + c0 + qr) * D_ + h * HD_ + l8 * 8;
            float4 v0 = ((const float4*)src)[0], v1 = ((const float4*)src)[1];
            *(float4*)&KV[qr * 68 + l8 * 8] = v0;
            *(float4*)&KV[qr * 68 + l8 * 8 + 4] = v1;
        }
        __syncthreads();
#pragma unroll
        for (int jj = 0; jj < QT; jj++) {
            float w = Sc[qr][c0 + jj];
            float4 v0 = *(const float4*)&KV[jj * 68 + d0];
            float4 v1 = *(const float4*)&KV[jj * 68 + d0 + 4];
            a0.x += w * v0.x; a0.y += w * v0.y; a0.z += w * v0.z; a0.w += w * v0.w;
            a1.x += w * v1.x; a1.y += w * v1.y; a1.z += w * v1.z; a1.w += w * v1.w;
        }
    }
    float* p = P + (size_t)(b * T_ + i) * D_ + h * HD_ + d0;
    ((float4*)p)[0] = a0;
    ((float4*)p)[1] = a1;
}

// ---------------------------------------------------------------------------
extern "C" void kernel_launch(void* const* d_in, const int* in_sizes, int n_in,
                              void* d_out, int out_size) {
    const float* x  = (const float*)d_in[0];
    const float* Wq = (const float*)d_in[1];
    const float* bq = (const float*)d_in[2];
    const float* Wk = (const float*)d_in[3];
    const float* bk = (const float*)d_in[4];
    const float* Wv = (const float*)d_in[5];
    const float* bv = (const float*)d_in[6];
    const float* Wo = (const float*)d_in[7];
    const float* bo = (const float*)d_in[8];
    float* out = (float*)d_out;

    const int has_attn = ((size_t)out_size >= OUT_ELEMS + ATTN_ELEMS) ? 1 : 0;

    float *pQ, *pK, *pV, *pP;
    __nv_bfloat16 *pA3, *pP3, *pW3;
    cudaGetSymbolAddress((void**)&pQ, g_Q);
    cudaGetSymbolAddress((void**)&pK, g_K);
    cudaGetSymbolAddress((void**)&pV, g_V);
    cudaGetSymbolAddress((void**)&pP, g_P);
    cudaGetSymbolAddress((void**)&pA3, g_A3);
    cudaGetSymbolAddress((void**)&pP3, g_P3);
    cudaGetSymbolAddress((void**)&pW3, g_W3);

    cudaFuncSetAttribute(gemm_hmma, cudaFuncAttributeMaxDynamicSharedMemorySize,
                         GSMEM);

    const int nA4 = MROWS * D_ / 4;
    const int nW4 = D_ * D_ / 4;
    cvt3v<<<(nA4 + 255) / 256, 256>>>(x, pA3, nA4, 4);                        // [h|h|l]
    cvt3v<<<(nW4 + 255) / 256, 256>>>(Wq, pW3 + 0 * (size_t)D_ * KE, nW4, 2); // [h|l|h]
    cvt3v<<<(nW4 + 255) / 256, 256>>>(Wk, pW3 + 1 * (size_t)D_ * KE, nW4, 2);
    cvt3v<<<(nW4 + 255) / 256, 256>>>(Wv, pW3 + 2 * (size_t)D_ * KE, nW4, 2);
    cvt3v<<<(nW4 + 255) / 256, 256>>>(Wo, pW3 + 3 * (size_t)D_ * KE, nW4, 2);

    // fused QKV: weight rows 0..3071 = Wq|Wk|Wv
    dim3 gqkv(3 * D_ / 128, MROWS / 128);   // (24, 32)
    gemm_hmma<<<gqkv, 256, GSMEM>>>(pA3, pW3, bq, bk, bv, pQ, pK, pV);

    dim3 agrid(T_ / QT, H_, B_);            // (64, 16, 2)
    attn2<<<agrid, 256>>>(pQ, pK, pV, pP,
                          has_attn ? (out + OUT_ELEMS) : out, has_attn);

    cvt3v<<<(nA4 + 255) / 256, 256>>>(pP, pP3, nA4, 4);
    dim3 go(D_ / 128, MROWS / 128);         // (8, 32)
    gemm_hmma<<<go, 256, GSMEM>>>(pP3, pW3 + 3 * (size_t)D_ * KE,
                                  bo, bo, bo, out, out, out);
}

// round 9
// speedup vs baseline: 2.8595x; 1.3782x over previous
#include <cuda_runtime.h>
#include <cuda_bf16.h>
#include <math.h>
#include <stdint.h>

// ---------------------------------------------------------------------------
// ALiBi self-attention. B=2, T=2048, D=1024, H=16, hd=64.
// sm_100 baseline: mma.sync m16n8k16 bf16 + ldmatrix + cp.async (no tcgen05).
//  * fused QKV GEMM (weight [3072,KE]); bf16 hi/lo split K 1024->3072.
//  * GEMM: 3-stage cp.async pipeline (hides L2 latency each chunk).
//  * attn3: banded attention, 2D register tiles (4qx4k QK, 4qx4d PV),
//    odd-stride (65) smem => conflict-free scalar LDS; P->P3 split fused in.
// ---------------------------------------------------------------------------

#define B_    2
#define T_    2048
#define D_    1024
#define H_    16
#define HD_   64
#define MROWS 4096
#define KE    3072
#define NCH   48
#define OUT_ELEMS  ((size_t)MROWS * D_)
#define ATTN_ELEMS ((size_t)B_ * H_ * T_ * T_)
#define WBACK 192

// ---------------- device scratch (allocation-free rule) --------------------
__device__ __align__(256) float g_Q[MROWS * D_];
__device__ __align__(256) float g_K[MROWS * D_];
__device__ __align__(256) float g_V[MROWS * D_];
__device__ __align__(256) __nv_bfloat16 g_A3[(size_t)MROWS * KE];
__device__ __align__(256) __nv_bfloat16 g_P3[(size_t)MROWS * KE];
__device__ __align__(256) __nv_bfloat16 g_W3[4][(size_t)D_ * KE];

// ---------------- PTX helpers ----------------------------------------------
__device__ __forceinline__ uint32_t s2u(const void* p) {
    uint32_t a;
    asm("{ .reg .u64 t; cvta.to.shared.u64 t, %1; cvt.u32.u64 %0, t; }"
        : "=r"(a) : "l"(p));
    return a;
}
__device__ __forceinline__ void cp16(uint32_t dst, const void* src) {
    asm volatile("cp.async.cg.shared.global [%0], [%1], 16;"
                 :: "r"(dst), "l"(src) : "memory");
}
#define CP_COMMIT() asm volatile("cp.async.commit_group;" ::: "memory")
#define CP_WAIT(n)  asm volatile("cp.async.wait_group %0;" :: "n"(n) : "memory")

__device__ __forceinline__ void ldsm4(uint32_t* r, uint32_t addr) {
    asm volatile("ldmatrix.sync.aligned.m8n8.x4.shared.b16 {%0,%1,%2,%3}, [%4];"
                 : "=r"(r[0]), "=r"(r[1]), "=r"(r[2]), "=r"(r[3]) : "r"(addr));
}
__device__ __forceinline__ void mma16816(float* c, const uint32_t* a,
                                         uint32_t b0, uint32_t b1) {
    asm volatile(
        "mma.sync.aligned.m16n8k16.row.col.f32.bf16.bf16.f32 "
        "{%0,%1,%2,%3}, {%4,%5,%6,%7}, {%8,%9}, {%0,%1,%2,%3};"
        : "+f"(c[0]), "+f"(c[1]), "+f"(c[2]), "+f"(c[3])
        : "r"(a[0]), "r"(a[1]), "r"(a[2]), "r"(a[3]), "r"(b0), "r"(b1));
}

// ---------------------------------------------------------------------------
// hi/lo split, 4 elems/thread: fp32 [rows,1024] -> bf16 [rows,3072]
// ---------------------------------------------------------------------------
__global__ void __launch_bounds__(256) cvt3v(const float* __restrict__ in,
                                             __nv_bfloat16* __restrict__ out,
                                             int n4, int loMask) {
    int i = blockIdx.x * 256 + threadIdx.x;
    if (i >= n4) return;
    float4 v = ((const float4*)in)[i];
    __nv_bfloat162 h01 = __floats2bfloat162_rn(v.x, v.y);
    __nv_bfloat162 h23 = __floats2bfloat162_rn(v.z, v.w);
    __nv_bfloat162 l01 = __floats2bfloat162_rn(v.x - __bfloat162float(h01.x),
                                               v.y - __bfloat162float(h01.y));
    __nv_bfloat162 l23 = __floats2bfloat162_rn(v.z - __bfloat162float(h23.x),
                                               v.w - __bfloat162float(h23.y));
    uint32_t h0 = *(uint32_t*)&h01, h1 = *(uint32_t*)&h23;
    uint32_t l0 = *(uint32_t*)&l01, l1 = *(uint32_t*)&l23;
    int idx = i * 4;
    int r = idx >> 10, k = idx & 1023;
    uint32_t* o = (uint32_t*)(out + (size_t)r * KE + k);
    o[0]    = (loMask & 1) ? l0 : h0;  o[1]    = (loMask & 1) ? l1 : h1;
    o[512]  = (loMask & 2) ? l0 : h0;  o[513]  = (loMask & 2) ? l1 : h1;
    o[1024] = (loMask & 4) ? l0 : h0;  o[1025] = (loMask & 4) ? l1 : h1;
}

// ---------------------------------------------------------------------------
// HMMA bf16 GEMM, 3-stage cp.async pipeline. CTA 128x128, 8 warps, 64x32/warp.
// ---------------------------------------------------------------------------
#define ROWB     144
#define TILEB    (128 * ROWB)
#define STAGEB   (2 * TILEB)          // 36864
#define GSMEM    (3 * STAGEB)         // 110592, 2 CTAs/SM

__global__ void __launch_bounds__(256, 2) gemm_hmma(
    const __nv_bfloat16* __restrict__ A3, const __nv_bfloat16* __restrict__ B3,
    const float* __restrict__ bias0, const float* __restrict__ bias1,
    const float* __restrict__ bias2,
    float* __restrict__ out0, float* __restrict__ out1, float* __restrict__ out2) {
    extern __shared__ __align__(128) char smem[];
    const uint32_t sb = s2u(smem);
    const int tid  = threadIdx.x;
    const int lane = tid & 31;
    const int w    = tid >> 5;
    const int wm   = (w & 1) * 64;
    const int wn   = (w >> 1) * 32;
    const int bm   = blockIdx.y * 128;
    const int bn   = blockIdx.x * 128;

    const int mat = bn >> 10;
    const float* bias = (mat == 0) ? bias0 : (mat == 1) ? bias1 : bias2;
    float* C          = (mat == 0) ? out0  : (mat == 1) ? out1  : out2;
    const int cn = bn & 1023;

    float acc[4][4][4];
#pragma unroll
    for (int i = 0; i < 4; i++)
#pragma unroll
        for (int j = 0; j < 4; j++)
#pragma unroll
            for (int q = 0; q < 4; q++) acc[i][j][q] = 0.f;

    const char* gAbase = (const char*)A3 + (size_t)bm * (KE * 2);
    const char* gBbase = (const char*)B3 + (size_t)bn * (KE * 2);

#define LOAD_STAGE(c, s)                                                      \
    do {                                                                      \
        uint32_t dA = sb + (s) * STAGEB;                                      \
        uint32_t dB = dA + TILEB;                                             \
        const char* sA = gAbase + (c) * 128;                                  \
        const char* sB = gBbase + (c) * 128;                                  \
        _Pragma("unroll")                                                     \
        for (int it = 0; it < 4; it++) {                                      \
            int u = tid + it * 256;                                           \
            int r = u >> 3, q = (u & 7) << 4;                                 \
            cp16(dA + r * ROWB + q, sA + (size_t)r * (KE * 2) + q);           \
            cp16(dB + r * ROWB + q, sB + (size_t)r * (KE * 2) + q);           \
        }                                                                     \
        CP_COMMIT();                                                          \
    } while (0)

    LOAD_STAGE(0, 0);
    LOAD_STAGE(1, 1);

    for (int c = 0; c < NCH; c++) {
        const int s = c - (c / 3) * 3;            // c % 3
        if (c + 1 < NCH) CP_WAIT(1); else CP_WAIT(0);
        __syncthreads();
        if (c + 2 < NCH) {
            int s2 = (c + 2) - ((c + 2) / 3) * 3;
            LOAD_STAGE(c + 2, s2);
        }

        const uint32_t aBase = sb + s * STAGEB +
                               (wm + (lane & 15)) * ROWB + ((lane >> 4) << 4);
        const uint32_t bBase = sb + s * STAGEB + TILEB +
                               (wn + (lane & 15)) * ROWB + ((lane >> 4) << 4);
#pragma unroll
        for (int kk = 0; kk < 4; kk++) {
            uint32_t af[4][4], bf[2][4];
#pragma unroll
            for (int i = 0; i < 4; i++)
                ldsm4(af[i], aBase + i * 16 * ROWB + kk * 32);
#pragma unroll
            for (int p = 0; p < 2; p++)
                ldsm4(bf[p], bBase + p * 16 * ROWB + kk * 32);
#pragma unroll
            for (int i = 0; i < 4; i++)
#pragma unroll
                for (int j = 0; j < 4; j++)
                    mma16816(acc[i][j], af[i], bf[j >> 1][j & 1],
                             bf[j >> 1][(j & 1) + 2]);
        }
    }

    const int g = lane >> 2, tg = lane & 3;
#pragma unroll
    for (int i = 0; i < 4; i++) {
#pragma unroll
        for (int j = 0; j < 4; j++) {
            int col  = cn + wn + j * 8 + tg * 2;
            float b0 = bias[col], b1 = bias[col + 1];
            int row0 = bm + wm + i * 16 + g;
            float2 v0 = make_float2(acc[i][j][0] + b0, acc[i][j][1] + b1);
            float2 v1 = make_float2(acc[i][j][2] + b0, acc[i][j][3] + b1);
            *(float2*)&C[(size_t)row0 * D_ + col]       = v0;
            *(float2*)&C[(size_t)(row0 + 8) * D_ + col] = v1;
        }
    }
}

// ---------------------------------------------------------------------------
// attn3: banded attention, 2D register tiling, odd-stride smem.
// Grid (T/32, H, B), 256 threads. smem (dynamic, 70.4KB):
//   Qs[32][65] | Ks[128][65] (K, then reused for V) | Sc[32][225]
// QK: thread (kg=tid>>3, qg=tid&7): 4 queries x 4 keys, chunks of 128 keys.
// PV: thread (hf=tid>>7, pg=(tid>>4)&7, dg=tid&15): 4 q x 4 d, key-halves.
// Epilogue writes P3 (bf16 hi|hi|lo) directly.
// ---------------------------------------------------------------------------
#define QS_OFF 0
#define KS_OFF (32 * 65)
#define SC_OFF (KS_OFF + 128 * 65)
#define ASMEM  ((SC_OFF + 32 * 225) * 4)    // 70400 B

__global__ void __launch_bounds__(256) attn3(
    const float* __restrict__ Q, const float* __restrict__ K,
    const float* __restrict__ V, __nv_bfloat16* __restrict__ P3,
    float* __restrict__ attn_out, int has_attn) {
    extern __shared__ float sm[];
    float* Qs = sm + QS_OFF;
    float* Ks = sm + KS_OFF;
    float* Sc = sm + SC_OFF;

    const int b = blockIdx.z, h = blockIdx.y;
    const int q0 = blockIdx.x * 32;
    const int tid = threadIdx.x;
    const int jlo = (q0 > WBACK) ? q0 - WBACK : 0;
    const int nk = q0 + 32 - jlo;               // multiple of 32, <= 224
    const size_t bT = (size_t)b * T_;

    // ---- load Q tile 32x64 (512 float4, 2/thread), stride-65 scalar store
#pragma unroll
    for (int i = 0; i < 2; i++) {
        int u = i * 256 + tid;
        int row = u >> 4, cu = u & 15;
        float4 v = *(const float4*)(Q + (bT + q0 + row) * D_ + h * HD_ + cu * 4);
        float* d = &Qs[row * 65 + cu * 4];
        d[0] = v.x; d[1] = v.y; d[2] = v.z; d[3] = v.w;
    }

    // ---- QK: scores into Sc (raw * 0.125)
    const int kg = tid >> 3, qg = tid & 7;
    for (int base = 0; base < nk; base += 128) {
        const int csize = (nk - base < 128) ? nk - base : 128;
        __syncthreads();
#pragma unroll
        for (int i = 0; i < 8; i++) {
            int u = i * 256 + tid;
            int row = u >> 4, cu = u & 15;
            if (row < csize) {
                float4 v = *(const float4*)(K + (bT + jlo + base + row) * D_ +
                                            h * HD_ + cu * 4);
                float* d = &Ks[row * 65 + cu * 4];
                d[0] = v.x; d[1] = v.y; d[2] = v.z; d[3] = v.w;
            }
        }
        __syncthreads();
        if (4 * kg < csize) {
            float acc[4][4];
#pragma unroll
            for (int i = 0; i < 4; i++)
#pragma unroll
                for (int j = 0; j < 4; j++) acc[i][j] = 0.f;
#pragma unroll 8
            for (int d = 0; d < 64; d++) {
                float qv[4], kv[4];
#pragma unroll
                for (int i = 0; i < 4; i++) qv[i] = Qs[(4 * qg + i) * 65 + d];
#pragma unroll
                for (int j = 0; j < 4; j++) kv[j] = Ks[(4 * kg + j) * 65 + d];
#pragma unroll
                for (int i = 0; i < 4; i++)
#pragma unroll
                    for (int j = 0; j < 4; j++) acc[i][j] += qv[i] * kv[j];
            }
#pragma unroll
            for (int i = 0; i < 4; i++)
#pragma unroll
                for (int j = 0; j < 4; j++)
                    Sc[(4 * qg + i) * 225 + base + 4 * kg + j] = acc[i][j] * 0.125f;
        }
    }
    __syncthreads();

    // ---- softmax per query row (8 lanes/row)
    const int qr = tid >> 3, l8 = tid & 7;
    const int iq = q0 + qr;
    float m = -1e30f;
    for (int idx = l8; idx < nk; idx += 8) {
        int j = jlo + idx;
        float sv = (j <= iq) ? (Sc[qr * 225 + idx] - (float)(iq - j)) : -1e30f;
        Sc[qr * 225 + idx] = sv;
        m = fmaxf(m, sv);
    }
#pragma unroll
    for (int o = 4; o >= 1; o >>= 1)
        m = fmaxf(m, __shfl_xor_sync(0xffffffffu, m, o, 8));
    float sum = 0.f;
    for (int idx = l8; idx < nk; idx += 8) {
        float sv = Sc[qr * 225 + idx];
        float e = (sv > -1e29f) ? expf(sv - m) : 0.f;
        Sc[qr * 225 + idx] = e;
        sum += e;
    }
#pragma unroll
    for (int o = 4; o >= 1; o >>= 1)
        sum += __shfl_xor_sync(0xffffffffu, sum, o, 8);
    float inv = 1.f / sum;
    for (int idx = l8; idx < nk; idx += 8)
        Sc[qr * 225 + idx] *= inv;
    __syncthreads();

    // ---- full attn row (float4, zeros outside band)
    if (has_attn) {
        float* row = attn_out + ((size_t)(b * H_ + h) * T_ + iq) * T_;
        for (int j4 = l8; j4 < T_ / 4; j4 += 8) {
            int j = j4 * 4;
            float4 v = make_float4(0.f, 0.f, 0.f, 0.f);
            if (j + 3 >= jlo && j <= iq) {
                int lo = j - jlo;
                v.x = (j + 0 >= jlo && j + 0 <= iq) ? Sc[qr * 225 + lo + 0] : 0.f;
                v.y = (j + 1 >= jlo && j + 1 <= iq) ? Sc[qr * 225 + lo + 1] : 0.f;
                v.z = (j + 2 >= jlo && j + 2 <= iq) ? Sc[qr * 225 + lo + 2] : 0.f;
                v.w = (j + 3 >= jlo && j + 3 <= iq) ? Sc[qr * 225 + lo + 3] : 0.f;
            }
            *(float4*)(row + j) = v;
        }
    }

    // ---- PV: 4q x 4d per thread, key-halves, V chunks reuse Ks
    const int hf = tid >> 7, pg = (tid >> 4) & 7, dg = tid & 15;
    float pacc[4][4];
#pragma unroll
    for (int i = 0; i < 4; i++)
#pragma unroll
        for (int t = 0; t < 4; t++) pacc[i][t] = 0.f;

    for (int base = 0; base < nk; base += 128) {
        const int csize = (nk - base < 128) ? nk - base : 128;
        __syncthreads();
#pragma unroll
        for (int i = 0; i < 8; i++) {
            int u = i * 256 + tid;
            int row = u >> 4, cu = u & 15;
            if (row < csize) {
                float4 v = *(const float4*)(V + (bT + jlo + base + row) * D_ +
                                            h * HD_ + cu * 4);
                float* d = &Ks[row * 65 + cu * 4];
                d[0] = v.x; d[1] = v.y; d[2] = v.z; d[3] = v.w;
            }
        }
        __syncthreads();
        const int half = csize >> 1;
        const int j0 = hf * half, j1 = j0 + half;
#pragma unroll 4
        for (int jj = j0; jj < j1; jj++) {
            float wv[4], vv[4];
#pragma unroll
            for (int i = 0; i < 4; i++)
                wv[i] = Sc[(4 * pg + i) * 225 + base + jj];
#pragma unroll
            for (int t = 0; t < 4; t++)
                vv[t] = Ks[jj * 65 + dg + 16 * t];
#pragma unroll
            for (int i = 0; i < 4; i++)
#pragma unroll
                for (int t = 0; t < 4; t++) pacc[i][t] += wv[i] * vv[t];
        }
    }
    __syncthreads();

    // ---- reduce halves via Qs, write P3 hi|hi|lo
    if (hf == 0) {
#pragma unroll
        for (int i = 0; i < 4; i++)
#pragma unroll
            for (int t = 0; t < 4; t++)
                Qs[(4 * pg + i) * 65 + dg + 16 * t] = pacc[i][t];
    }
    __syncthreads();
    if (hf == 1) {
#pragma unroll
        for (int i = 0; i < 4; i++) {
#pragma unroll
            for (int t = 0; t < 4; t++) {
                float v = pacc[i][t] + Qs[(4 * pg + i) * 65 + dg + 16 * t];
                __nv_bfloat16 hh = __float2bfloat16(v);
                __nv_bfloat16 ll = __float2bfloat16(v - __bfloat162float(hh));
                __nv_bfloat16* p = P3 + (bT + q0 + 4 * pg + i) * KE +
                                   h * HD_ + dg + 16 * t;
                p[0] = hh; p[1024] = hh; p[2048] = ll;
            }
        }
    }
}

// ---------------------------------------------------------------------------
extern "C" void kernel_launch(void* const* d_in, const int* in_sizes, int n_in,
                              void* d_out, int out_size) {
    const float* x  = (const float*)d_in[0];
    const float* Wq = (const float*)d_in[1];
    const float* bq = (const float*)d_in[2];
    const float* Wk = (const float*)d_in[3];
    const float* bk = (const float*)d_in[4];
    const float* Wv = (const float*)d_in[5];
    const float* bv = (const float*)d_in[6];
    const float* Wo = (const float*)d_in[7];
    const float* bo = (const float*)d_in[8];
    float* out = (float*)d_out;

    const int has_attn = ((size_t)out_size >= OUT_ELEMS + ATTN_ELEMS) ? 1 : 0;

    float *pQ, *pK, *pV;
    __nv_bfloat16 *pA3, *pP3, *pW3;
    cudaGetSymbolAddress((void**)&pQ, g_Q);
    cudaGetSymbolAddress((void**)&pK, g_K);
    cudaGetSymbolAddress((void**)&pV, g_V);
    cudaGetSymbolAddress((void**)&pA3, g_A3);
    cudaGetSymbolAddress((void**)&pP3, g_P3);
    cudaGetSymbolAddress((void**)&pW3, g_W3);

    cudaFuncSetAttribute(gemm_hmma, cudaFuncAttributeMaxDynamicSharedMemorySize,
                         GSMEM);
    cudaFuncSetAttribute(attn3, cudaFuncAttributeMaxDynamicSharedMemorySize,
                         ASMEM);

    const int nA4 = MROWS * D_ / 4;
    const int nW4 = D_ * D_ / 4;
    cvt3v<<<(nA4 + 255) / 256, 256>>>(x, pA3, nA4, 4);                        // [h|h|l]
    cvt3v<<<(nW4 + 255) / 256, 256>>>(Wq, pW3 + 0 * (size_t)D_ * KE, nW4, 2); // [h|l|h]
    cvt3v<<<(nW4 + 255) / 256, 256>>>(Wk, pW3 + 1 * (size_t)D_ * KE, nW4, 2);
    cvt3v<<<(nW4 + 255) / 256, 256>>>(Wv, pW3 + 2 * (size_t)D_ * KE, nW4, 2);
    cvt3v<<<(nW4 + 255) / 256, 256>>>(Wo, pW3 + 3 * (size_t)D_ * KE, nW4, 2);

    dim3 gqkv(3 * D_ / 128, MROWS / 128);   // (24, 32)
    gemm_hmma<<<gqkv, 256, GSMEM>>>(pA3, pW3, bq, bk, bv, pQ, pK, pV);

    dim3 agrid(T_ / 32, H_, B_);            // (64, 16, 2)
    attn3<<<agrid, 256, ASMEM>>>(pQ, pK, pV, pP3,
                                 has_attn ? (out + OUT_ELEMS) : out, has_attn);

    dim3 go(D_ / 128, MROWS / 128);         // (8, 32)
    gemm_hmma<<<go, 256, GSMEM>>>(pP3, pW3 + 3 * (size_t)D_ * KE,
                                  bo, bo, bo, out, out, out);
}

// round 10
// speedup vs baseline: 2.8757x; 1.0057x over previous
#include <cuda_runtime.h>
#include <cuda_bf16.h>
#include <math.h>
#include <stdint.h>

// ---------------------------------------------------------------------------
// ALiBi self-attention. B=2, T=2048, D=1024, H=16, hd=64.
// sm_100 baseline: mma.sync m16n8k16 bf16 + ldmatrix + cp.async (no tcgen05).
//  * fused QKV GEMM (weight [3072,KE]); bf16 hi/lo split K 1024->3072.
//  * GEMM: 64x64 warp tiles (4 warps/CTA) -- ldsm:mma 8:32 (was 6:8, smem-BW
//    bound at ~2x tensor floor); 3-stage cp.async pipeline.
//  * attn3: banded attention, 2D register tiles, odd-stride smem,
//    P->P3 hi/lo split fused into PV epilogue.
// ---------------------------------------------------------------------------

#define B_    2
#define T_    2048
#define D_    1024
#define H_    16
#define HD_   64
#define MROWS 4096
#define KE    3072
#define NCH   48
#define OUT_ELEMS  ((size_t)MROWS * D_)
#define ATTN_ELEMS ((size_t)B_ * H_ * T_ * T_)
#define WBACK 192

// ---------------- device scratch (allocation-free rule) --------------------
__device__ __align__(256) float g_Q[MROWS * D_];
__device__ __align__(256) float g_K[MROWS * D_];
__device__ __align__(256) float g_V[MROWS * D_];
__device__ __align__(256) __nv_bfloat16 g_A3[(size_t)MROWS * KE];
__device__ __align__(256) __nv_bfloat16 g_P3[(size_t)MROWS * KE];
__device__ __align__(256) __nv_bfloat16 g_W3[4][(size_t)D_ * KE];

// ---------------- PTX helpers ----------------------------------------------
__device__ __forceinline__ uint32_t s2u(const void* p) {
    uint32_t a;
    asm("{ .reg .u64 t; cvta.to.shared.u64 t, %1; cvt.u32.u64 %0, t; }"
        : "=r"(a) : "l"(p));
    return a;
}
__device__ __forceinline__ void cp16(uint32_t dst, const void* src) {
    asm volatile("cp.async.cg.shared.global [%0], [%1], 16;"
                 :: "r"(dst), "l"(src) : "memory");
}
#define CP_COMMIT() asm volatile("cp.async.commit_group;" ::: "memory")
#define CP_WAIT(n)  asm volatile("cp.async.wait_group %0;" :: "n"(n) : "memory")

__device__ __forceinline__ void ldsm4(uint32_t* r, uint32_t addr) {
    asm volatile("ldmatrix.sync.aligned.m8n8.x4.shared.b16 {%0,%1,%2,%3}, [%4];"
                 : "=r"(r[0]), "=r"(r[1]), "=r"(r[2]), "=r"(r[3]) : "r"(addr));
}
__device__ __forceinline__ void mma16816(float* c, const uint32_t* a,
                                         uint32_t b0, uint32_t b1) {
    asm volatile(
        "mma.sync.aligned.m16n8k16.row.col.f32.bf16.bf16.f32 "
        "{%0,%1,%2,%3}, {%4,%5,%6,%7}, {%8,%9}, {%0,%1,%2,%3};"
        : "+f"(c[0]), "+f"(c[1]), "+f"(c[2]), "+f"(c[3])
        : "r"(a[0]), "r"(a[1]), "r"(a[2]), "r"(a[3]), "r"(b0), "r"(b1));
}

// ---------------------------------------------------------------------------
// hi/lo split kernels: fp32 [rows,1024] -> bf16 [rows,3072]
// ---------------------------------------------------------------------------
__device__ __forceinline__ void split_store(const float* __restrict__ in,
                                            __nv_bfloat16* __restrict__ out,
                                            int i, int loMask) {
    float4 v = ((const float4*)in)[i];
    __nv_bfloat162 h01 = __floats2bfloat162_rn(v.x, v.y);
    __nv_bfloat162 h23 = __floats2bfloat162_rn(v.z, v.w);
    __nv_bfloat162 l01 = __floats2bfloat162_rn(v.x - __bfloat162float(h01.x),
                                               v.y - __bfloat162float(h01.y));
    __nv_bfloat162 l23 = __floats2bfloat162_rn(v.z - __bfloat162float(h23.x),
                                               v.w - __bfloat162float(h23.y));
    uint32_t h0 = *(uint32_t*)&h01, h1 = *(uint32_t*)&h23;
    uint32_t l0 = *(uint32_t*)&l01, l1 = *(uint32_t*)&l23;
    int idx = i * 4;
    int r = idx >> 10, k = idx & 1023;
    uint32_t* o = (uint32_t*)(out + (size_t)r * KE + k);
    o[0]    = (loMask & 1) ? l0 : h0;  o[1]    = (loMask & 1) ? l1 : h1;
    o[512]  = (loMask & 2) ? l0 : h0;  o[513]  = (loMask & 2) ? l1 : h1;
    o[1024] = (loMask & 4) ? l0 : h0;  o[1025] = (loMask & 4) ? l1 : h1;
}

__global__ void __launch_bounds__(256) cvt3v(const float* __restrict__ in,
                                             __nv_bfloat16* __restrict__ out,
                                             int n4, int loMask) {
    int i = blockIdx.x * 256 + threadIdx.x;
    if (i < n4) split_store(in, out, i, loMask);
}

// all 4 weights in one launch: blockIdx.y selects the matrix. loMask=2 [h|l|h]
__global__ void __launch_bounds__(256) cvtW(const float* __restrict__ w0,
                                            const float* __restrict__ w1,
                                            const float* __restrict__ w2,
                                            const float* __restrict__ w3,
                                            __nv_bfloat16* __restrict__ outBase,
                                            int n4) {
    int i = blockIdx.x * 256 + threadIdx.x;
    if (i >= n4) return;
    int m = blockIdx.y;
    const float* in = (m == 0) ? w0 : (m == 1) ? w1 : (m == 2) ? w2 : w3;
    split_store(in, outBase + (size_t)m * D_ * KE, i, 2);
}

// ---------------------------------------------------------------------------
// HMMA bf16 GEMM, CTA 128x128, 4 warps (2x2), warp tile 64x64.
// 3-stage cp.async pipeline, 128 threads, 2 CTAs/SM.
// ---------------------------------------------------------------------------
#define ROWB     144
#define TILEB    (128 * ROWB)
#define STAGEB   (2 * TILEB)          // 36864
#define GSMEM    (3 * STAGEB)         // 110592

__global__ void __launch_bounds__(128, 2) gemm_hmma(
    const __nv_bfloat16* __restrict__ A3, const __nv_bfloat16* __restrict__ B3,
    const float* __restrict__ bias0, const float* __restrict__ bias1,
    const float* __restrict__ bias2,
    float* __restrict__ out0, float* __restrict__ out1, float* __restrict__ out2) {
    extern __shared__ __align__(128) char smem[];
    const uint32_t sb = s2u(smem);
    const int tid  = threadIdx.x;
    const int lane = tid & 31;
    const int w    = tid >> 5;
    const int wm   = (w & 1) * 64;
    const int wn   = (w >> 1) * 64;
    const int bm   = blockIdx.y * 128;
    const int bn   = blockIdx.x * 128;

    const int mat = bn >> 10;
    const float* bias = (mat == 0) ? bias0 : (mat == 1) ? bias1 : bias2;
    float* C          = (mat == 0) ? out0  : (mat == 1) ? out1  : out2;
    const int cn = bn & 1023;

    float acc[4][8][4];
#pragma unroll
    for (int i = 0; i < 4; i++)
#pragma unroll
        for (int j = 0; j < 8; j++)
#pragma unroll
            for (int q = 0; q < 4; q++) acc[i][j][q] = 0.f;

    const char* gAbase = (const char*)A3 + (size_t)bm * (KE * 2);
    const char* gBbase = (const char*)B3 + (size_t)bn * (KE * 2);

#define LOAD_STAGE(c, s)                                                      \
    do {                                                                      \
        uint32_t dA = sb + (s) * STAGEB;                                      \
        uint32_t dB = dA + TILEB;                                             \
        const char* sA = gAbase + (c) * 128;                                  \
        const char* sB = gBbase + (c) * 128;                                  \
        _Pragma("unroll")                                                     \
        for (int it = 0; it < 8; it++) {                                      \
            int u = tid + it * 128;                                           \
            int r = u >> 3, q = (u & 7) << 4;                                 \
            cp16(dA + r * ROWB + q, sA + (size_t)r * (KE * 2) + q);           \
            cp16(dB + r * ROWB + q, sB + (size_t)r * (KE * 2) + q);           \
        }                                                                     \
        CP_COMMIT();                                                          \
    } while (0)

    LOAD_STAGE(0, 0);
    LOAD_STAGE(1, 1);

    for (int c = 0; c < NCH; c++) {
        const int s = c - (c / 3) * 3;            // c % 3
        if (c + 1 < NCH) CP_WAIT(1); else CP_WAIT(0);
        __syncthreads();
        if (c + 2 < NCH) {
            int s2 = (c + 2) - ((c + 2) / 3) * 3;
            LOAD_STAGE(c + 2, s2);
        }

        const uint32_t aBase = sb + s * STAGEB +
                               (wm + (lane & 15)) * ROWB + ((lane >> 4) << 4);
        const uint32_t bBase = sb + s * STAGEB + TILEB +
                               (wn + (lane & 15)) * ROWB + ((lane >> 4) << 4);
#pragma unroll
        for (int kk = 0; kk < 4; kk++) {
            uint32_t af[4][4], bf[4][4];
#pragma unroll
            for (int i = 0; i < 4; i++)
                ldsm4(af[i], aBase + i * 16 * ROWB + kk * 32);
#pragma unroll
            for (int p = 0; p < 4; p++)
                ldsm4(bf[p], bBase + p * 16 * ROWB + kk * 32);
            // n-atom j: pair p=j>>1, half h=j&1: b0=bf[p][h], b1=bf[p][h+2]
#pragma unroll
            for (int i = 0; i < 4; i++)
#pragma unroll
                for (int j = 0; j < 8; j++)
                    mma16816(acc[i][j], af[i], bf[j >> 1][j & 1],
                             bf[j >> 1][(j & 1) + 2]);
        }
    }

    const int g = lane >> 2, tg = lane & 3;
#pragma unroll
    for (int i = 0; i < 4; i++) {
#pragma unroll
        for (int j = 0; j < 8; j++) {
            int col  = cn + wn + j * 8 + tg * 2;
            float b0 = bias[col], b1 = bias[col + 1];
            int row0 = bm + wm + i * 16 + g;
            float2 v0 = make_float2(acc[i][j][0] + b0, acc[i][j][1] + b1);
            float2 v1 = make_float2(acc[i][j][2] + b0, acc[i][j][3] + b1);
            *(float2*)&C[(size_t)row0 * D_ + col]       = v0;
            *(float2*)&C[(size_t)(row0 + 8) * D_ + col] = v1;
        }
    }
}

// ---------------------------------------------------------------------------
// attn3: banded attention, 2D register tiling, odd-stride smem. (unchanged)
// ---------------------------------------------------------------------------
#define QS_OFF 0
#define KS_OFF (32 * 65)
#define SC_OFF (KS_OFF + 128 * 65)
#define ASMEM  ((SC_OFF + 32 * 225) * 4)    // 70400 B

__global__ void __launch_bounds__(256) attn3(
    const float* __restrict__ Q, const float* __restrict__ K,
    const float* __restrict__ V, __nv_bfloat16* __restrict__ P3,
    float* __restrict__ attn_out, int has_attn) {
    extern __shared__ float sm[];
    float* Qs = sm + QS_OFF;
    float* Ks = sm + KS_OFF;
    float* Sc = sm + SC_OFF;

    const int b = blockIdx.z, h = blockIdx.y;
    const int q0 = blockIdx.x * 32;
    const int tid = threadIdx.x;
    const int jlo = (q0 > WBACK) ? q0 - WBACK : 0;
    const int nk = q0 + 32 - jlo;
    const size_t bT = (size_t)b * T_;

#pragma unroll
    for (int i = 0; i < 2; i++) {
        int u = i * 256 + tid;
        int row = u >> 4, cu = u & 15;
        float4 v = *(const float4*)(Q + (bT + q0 + row) * D_ + h * HD_ + cu * 4);
        float* d = &Qs[row * 65 + cu * 4];
        d[0] = v.x; d[1] = v.y; d[2] = v.z; d[3] = v.w;
    }

    const int kg = tid >> 3, qg = tid & 7;
    for (int base = 0; base < nk; base += 128) {
        const int csize = (nk - base < 128) ? nk - base : 128;
        __syncthreads();
#pragma unroll
        for (int i = 0; i < 8; i++) {
            int u = i * 256 + tid;
            int row = u >> 4, cu = u & 15;
            if (row < csize) {
                float4 v = *(const float4*)(K + (bT + jlo + base + row) * D_ +
                                            h * HD_ + cu * 4);
                float* d = &Ks[row * 65 + cu * 4];
                d[0] = v.x; d[1] = v.y; d[2] = v.z; d[3] = v.w;
            }
        }
        __syncthreads();
        if (4 * kg < csize) {
            float acc[4][4];
#pragma unroll
            for (int i = 0; i < 4; i++)
#pragma unroll
                for (int j = 0; j < 4; j++) acc[i][j] = 0.f;
#pragma unroll 8
            for (int d = 0; d < 64; d++) {
                float qv[4], kv[4];
#pragma unroll
                for (int i = 0; i < 4; i++) qv[i] = Qs[(4 * qg + i) * 65 + d];
#pragma unroll
                for (int j = 0; j < 4; j++) kv[j] = Ks[(4 * kg + j) * 65 + d];
#pragma unroll
                for (int i = 0; i < 4; i++)
#pragma unroll
                    for (int j = 0; j < 4; j++) acc[i][j] += qv[i] * kv[j];
            }
#pragma unroll
            for (int i = 0; i < 4; i++)
#pragma unroll
                for (int j = 0; j < 4; j++)
                    Sc[(4 * qg + i) * 225 + base + 4 * kg + j] = acc[i][j] * 0.125f;
        }
    }
    __syncthreads();

    const int qr = tid >> 3, l8 = tid & 7;
    const int iq = q0 + qr;
    float m = -1e30f;
    for (int idx = l8; idx < nk; idx += 8) {
        int j = jlo + idx;
        float sv = (j <= iq) ? (Sc[qr * 225 + idx] - (float)(iq - j)) : -1e30f;
        Sc[qr * 225 + idx] = sv;
        m = fmaxf(m, sv);
    }
#pragma unroll
    for (int o = 4; o >= 1; o >>= 1)
        m = fmaxf(m, __shfl_xor_sync(0xffffffffu, m, o, 8));
    float sum = 0.f;
    for (int idx = l8; idx < nk; idx += 8) {
        float sv = Sc[qr * 225 + idx];
        float e = (sv > -1e29f) ? expf(sv - m) : 0.f;
        Sc[qr * 225 + idx] = e;
        sum += e;
    }
#pragma unroll
    for (int o = 4; o >= 1; o >>= 1)
        sum += __shfl_xor_sync(0xffffffffu, sum, o, 8);
    float inv = 1.f / sum;
    for (int idx = l8; idx < nk; idx += 8)
        Sc[qr * 225 + idx] *= inv;
    __syncthreads();

    if (has_attn) {
        float* row = attn_out + ((size_t)(b * H_ + h) * T_ + iq) * T_;
        for (int j4 = l8; j4 < T_ / 4; j4 += 8) {
            int j = j4 * 4;
            float4 v = make_float4(0.f, 0.f, 0.f, 0.f);
            if (j + 3 >= jlo && j <= iq) {
                int lo = j - jlo;
                v.x = (j + 0 >= jlo && j + 0 <= iq) ? Sc[qr * 225 + lo + 0] : 0.f;
                v.y = (j + 1 >= jlo && j + 1 <= iq) ? Sc[qr * 225 + lo + 1] : 0.f;
                v.z = (j + 2 >= jlo && j + 2 <= iq) ? Sc[qr * 225 + lo + 2] : 0.f;
                v.w = (j + 3 >= jlo && j + 3 <= iq) ? Sc[qr * 225 + lo + 3] : 0.f;
            }
            *(float4*)(row + j) = v;
        }
    }

    const int hf = tid >> 7, pg = (tid >> 4) & 7, dg = tid & 15;
    float pacc[4][4];
#pragma unroll
    for (int i = 0; i < 4; i++)
#pragma unroll
        for (int t = 0; t < 4; t++) pacc[i][t] = 0.f;

    for (int base = 0; base < nk; base += 128) {
        const int csize = (nk - base < 128) ? nk - base : 128;
        __syncthreads();
#pragma unroll
        for (int i = 0; i < 8; i++) {
            int u = i * 256 + tid;
            int row = u >> 4, cu = u & 15;
            if (row < csize) {
                float4 v = *(const float4*)(V + (bT + jlo + base + row) * D_ +
                                            h * HD_ + cu * 4);
                float* d = &Ks[row * 65 + cu * 4];
                d[0] = v.x; d[1] = v.y; d[2] = v.z; d[3] = v.w;
            }
        }
        __syncthreads();
        const int half = csize >> 1;
        const int j0 = hf * half, j1 = j0 + half;
#pragma unroll 4
        for (int jj = j0; jj < j1; jj++) {
            float wv[4], vv[4];
#pragma unroll
            for (int i = 0; i < 4; i++)
                wv[i] = Sc[(4 * pg + i) * 225 + base + jj];
#pragma unroll
            for (int t = 0; t < 4; t++)
                vv[t] = Ks[jj * 65 + dg + 16 * t];
#pragma unroll
            for (int i = 0; i < 4; i++)
#pragma unroll
                for (int t = 0; t < 4; t++) pacc[i][t] += wv[i] * vv[t];
        }
    }
    __syncthreads();

    if (hf == 0) {
#pragma unroll
        for (int i = 0; i < 4; i++)
#pragma unroll
            for (int t = 0; t < 4; t++)
                Qs[(4 * pg + i) * 65 + dg + 16 * t] = pacc[i][t];
    }
    __syncthreads();
    if (hf == 1) {
#pragma unroll
        for (int i = 0; i < 4; i++) {
#pragma unroll
            for (int t = 0; t < 4; t++) {
                float v = pacc[i][t] + Qs[(4 * pg + i) * 65 + dg + 16 * t];
                __nv_bfloat16 hh = __float2bfloat16(v);
                __nv_bfloat16 ll = __float2bfloat16(v - __bfloat162float(hh));
                __nv_bfloat16* p = P3 + (bT + q0 + 4 * pg + i) * KE +
                                   h * HD_ + dg + 16 * t;
                p[0] = hh; p[1024] = hh; p[2048] = ll;
            }
        }
    }
}

// ---------------------------------------------------------------------------
extern "C" void kernel_launch(void* const* d_in, const int* in_sizes, int n_in,
                              void* d_out, int out_size) {
    const float* x  = (const float*)d_in[0];
    const float* Wq = (const float*)d_in[1];
    const float* bq = (const float*)d_in[2];
    const float* Wk = (const float*)d_in[3];
    const float* bk = (const float*)d_in[4];
    const float* Wv = (const float*)d_in[5];
    const float* bv = (const float*)d_in[6];
    const float* Wo = (const float*)d_in[7];
    const float* bo = (const float*)d_in[8];
    float* out = (float*)d_out;

    const int has_attn = ((size_t)out_size >= OUT_ELEMS + ATTN_ELEMS) ? 1 : 0;

    float *pQ, *pK, *pV;
    __nv_bfloat16 *pA3, *pP3, *pW3;
    cudaGetSymbolAddress((void**)&pQ, g_Q);
    cudaGetSymbolAddress((void**)&pK, g_K);
    cudaGetSymbolAddress((void**)&pV, g_V);
    cudaGetSymbolAddress((void**)&pA3, g_A3);
    cudaGetSymbolAddress((void**)&pP3, g_P3);
    cudaGetSymbolAddress((void**)&pW3, g_W3);

    cudaFuncSetAttribute(gemm_hmma, cudaFuncAttributeMaxDynamicSharedMemorySize,
                         GSMEM);
    cudaFuncSetAttribute(attn3, cudaFuncAttributeMaxDynamicSharedMemorySize,
                         ASMEM);

    const int nA4 = MROWS * D_ / 4;
    const int nW4 = D_ * D_ / 4;
    cvt3v<<<(nA4 + 255) / 256, 256>>>(x, pA3, nA4, 4);        // [h|h|l]
    dim3 wg((nW4 + 255) / 256, 4);
    cvtW<<<wg, 256>>>(Wq, Wk, Wv, Wo, pW3, nW4);              // [h|l|h] x4

    dim3 gqkv(3 * D_ / 128, MROWS / 128);   // (24, 32)
    gemm_hmma<<<gqkv, 128, GSMEM>>>(pA3, pW3, bq, bk, bv, pQ, pK, pV);

    dim3 agrid(T_ / 32, H_, B_);            // (64, 16, 2)
    attn3<<<agrid, 256, ASMEM>>>(pQ, pK, pV, pP3,
                                 has_attn ? (out + OUT_ELEMS) : out, has_attn);

    dim3 go(D_ / 128, MROWS / 128);         // (8, 32)
    gemm_hmma<<<go, 128, GSMEM>>>(pP3, pW3 + 3 * (size_t)D_ * KE,
                                  bo, bo, bo, out, out, out);
}